// round 6
// baseline (speedup 1.0000x reference)
#include <cuda_runtime.h>
#include <cstddef>

#define TT_STEPS 365
#define NB 4000
#define MM 4
#define LENF 15

// Scratch (allocation-free: __device__ globals)
__device__ float g_qsim[TT_STEPS * NB];   // mean-over-M runoff per (t, n)
__device__ float g_uh[LENF * NB];         // routing weights per (k, n)

// -------------------------------------------------------------------------
// Kernel 1: HBV scan. One thread per (n, m) chain; 16000 threads total.
// Software-pipelined: step t+1's 17 loads are issued before step t's math.
// -------------------------------------------------------------------------
__device__ __forceinline__ void load_step(const float* __restrict__ pbase,
                                          const float* __restrict__ xbase,
                                          int t, float pr[14], float fr[3]) {
    size_t poff = (size_t)t * (NB * 64);
#pragma unroll
    for (int i = 0; i < 14; ++i)
        pr[i] = __ldg(pbase + poff + i * 4);
    size_t xoff = (size_t)t * (NB * 3);
#pragma unroll
    for (int c = 0; c < 3; ++c)
        fr[c] = __ldg(xbase + xoff + c);
}

__global__ void __launch_bounds__(128)
hbv_scan_kernel(const float* __restrict__ x,        // (T, N, 3)
                const float* __restrict__ praw) {   // (T, N, 16, M)
    const int tid = blockIdx.x * 128 + threadIdx.x; // exactly 16000 threads
    const int n = tid >> 2;
    const int m = tid & 3;

    const float* pbase = praw + (size_t)n * 64 + m;
    const float* xbase = x + (size_t)n * 3;

    float SNOWPACK = 0.001f, MELTWATER = 0.001f, SM = 0.001f,
          SUZ = 0.001f, SLZ = 0.001f;

    float cur[14], fc[3];
    load_step(pbase, xbase, 0, cur, fc);

    for (int t = 0; t < TT_STEPS; ++t) {
        float nxt[14], fn[3];
        const int tn = (t + 1 < TT_STEPS) ? (t + 1) : t;
        load_step(pbase, xbase, tn, nxt, fn);   // prefetch (independent of math below)

        // ---- scale raw params to physical bounds ----
        const float BETA   = 1.0f   + 5.0f    * cur[0];
        const float FC     = 50.0f  + 950.0f  * cur[1];
        const float K0     = 0.05f  + 0.85f   * cur[2];
        const float K1     = 0.01f  + 0.49f   * cur[3];
        const float K2     = 0.001f + 0.199f  * cur[4];
        const float LP     = 0.2f   + 0.8f    * cur[5];
        const float PERC   =          10.0f   * cur[6];
        const float UZL    =          100.0f  * cur[7];
        const float TTp    = -2.5f  + 5.0f    * cur[8];
        const float CFMAX  = 0.5f   + 9.5f    * cur[9];
        const float CFR    =          0.1f    * cur[10];
        const float CWH    =          0.2f    * cur[11];
        const float BETAET = 0.3f   + 4.7f    * cur[12];
        const float Cc     =                    cur[13];

        const float P   = fc[0];
        const float Ta  = fc[1];
        const float PET = fc[2];

        // ---- HBV step (exact reference op order) ----
        const float RAIN = (Ta >= TTp) ? P : 0.0f;
        const float SNOW = (Ta <  TTp) ? P : 0.0f;
        SNOWPACK += SNOW;
        const float melt = fminf(fmaxf(CFMAX * (Ta - TTp), 0.0f), SNOWPACK);
        MELTWATER += melt;
        SNOWPACK = fmaxf(SNOWPACK - melt, 1e-5f);
        const float refreeze = fminf(fmaxf(CFR * CFMAX * (TTp - Ta), 0.0f), MELTWATER);
        SNOWPACK += refreeze;
        MELTWATER = fmaxf(MELTWATER - refreeze, 1e-5f);
        const float tosoil = fmaxf(MELTWATER - CWH * SNOWPACK, 0.0f);
        MELTWATER = fmaxf(MELTWATER - tosoil, 1e-5f);

        const float rFC = __fdividef(1.0f, FC);
        float soil_wet = __expf(BETA * __logf(SM * rFC));
        soil_wet = fminf(fmaxf(soil_wet, 0.0f), 1.0f);
        const float recharge = (RAIN + tosoil) * soil_wet;
        SM = SM + RAIN + tosoil - recharge;
        const float excess = fmaxf(SM - FC, 0.0f);
        SM = fmaxf(SM - excess, 1e-5f);

        float evapfactor = __expf(BETAET * __logf(SM * __fdividef(1.0f, LP * FC)));
        evapfactor = fminf(fmaxf(evapfactor, 0.0f), 1.0f);
        const float ETact = fminf(SM, PET * evapfactor);
        SM = fmaxf(SM - ETact, 1e-5f);

        const float capillary = fminf(SLZ, Cc * SLZ * (1.0f - fminf(SM * rFC, 1.0f)));
        SM += capillary;
        SLZ = fmaxf(SLZ - capillary, 1e-5f);

        SUZ += recharge + excess;
        const float PERCa = fminf(SUZ, PERC);
        SUZ -= PERCa;
        const float Q0 = K0 * fmaxf(SUZ - UZL, 0.0f);
        SUZ -= Q0;
        const float Q1 = K1 * SUZ;
        SUZ -= Q1;
        SLZ += PERCa;
        const float Q2 = K2 * SLZ;
        SLZ -= Q2;

        // mean over the 4 ensemble members (quad = adjacent lanes)
        float q = Q0 + Q1 + Q2;
        q += __shfl_xor_sync(0xffffffffu, q, 1);
        q += __shfl_xor_sync(0xffffffffu, q, 2);
        if (m == 0)
            g_qsim[(size_t)t * NB + n] = 0.25f * q;

#pragma unroll
        for (int i = 0; i < 14; ++i) cur[i] = nxt[i];
#pragma unroll
        for (int c = 0; c < 3; ++c) fc[c] = fn[c];
    }
}

// -------------------------------------------------------------------------
// Kernel 2: gamma unit-hydrograph weights per basin (normalized).
// -------------------------------------------------------------------------
__global__ void uh_kernel(const float* __restrict__ conv) {
    const int n = blockIdx.x * blockDim.x + threadIdx.x;
    if (n >= NB) return;
    const float a = conv[n * 2 + 0] * 2.9f;
    const float b = conv[n * 2 + 1] * 6.5f;
    const float aa    = fmaxf(a, 0.0f) + 0.1f;
    const float theta = fmaxf(b, 0.0f) + 0.5f;
    const float lg = lgammaf(aa);
    const float lt = logf(theta);
    const float rth = 1.0f / theta;

    float w[LENF];
    float s = 0.0f;
#pragma unroll
    for (int k = 0; k < LENF; ++k) {
        const float tt = 0.5f + (float)k;
        w[k] = expf(-lg - aa * lt + (aa - 1.0f) * logf(tt) - tt * rth);
        s += w[k];
    }
    const float rs = 1.0f / s;
#pragma unroll
    for (int k = 0; k < LENF; ++k)
        g_uh[k * NB + n] = w[k] * rs;
}

// -------------------------------------------------------------------------
// Kernel 3: 15-tap causal FIR routing. One thread per (t, n) output.
// -------------------------------------------------------------------------
__global__ void rout_kernel(float* __restrict__ out) {
    const int idx = blockIdx.x * blockDim.x + threadIdx.x;
    if (idx >= TT_STEPS * NB) return;
    const int t = idx / NB;
    const int n = idx - t * NB;

    float acc = 0.0f;
#pragma unroll
    for (int k = 0; k < LENF; ++k) {
        if (k <= t)
            acc += __ldg(&g_uh[k * NB + n]) * __ldg(&g_qsim[(size_t)(t - k) * NB + n]);
    }
    out[idx] = acc;
}

// -------------------------------------------------------------------------
extern "C" void kernel_launch(void* const* d_in, const int* in_sizes, int n_in,
                              void* d_out, int out_size) {
    const float* x    = (const float*)d_in[0];   // (365, 4000, 3)
    const float* praw = (const float*)d_in[1];   // (365, 4000, 16, 4)
    const float* conv = (const float*)d_in[2];   // (4000, 2)
    float* out = (float*)d_out;                  // (365, 4000)

    hbv_scan_kernel<<<(NB * MM) / 128, 128>>>(x, praw);
    uh_kernel<<<(NB + 127) / 128, 128>>>(conv);
    rout_kernel<<<(TT_STEPS * NB + 255) / 256, 256>>>(out);
}

// round 7
// speedup vs baseline: 1.1856x; 1.1856x over previous
#include <cuda_runtime.h>
#include <cstddef>

#define TT_STEPS 365
#define NB 4000
#define MM 4
#define LENF 15

// Scratch (allocation-free: __device__ globals)
__device__ float g_qsim[TT_STEPS * NB];   // mean-over-M runoff per (t, n)
__device__ float g_uh[LENF * NB];         // routing weights per (k, n)

#define STAGES 3
#define BSTRIDE 68                       // 64 floats + 4 pad -> conflict-free LDS
#define STAGE_FLOATS (8 * BSTRIDE)       // 544 floats = 2176 B per warp-stage

__device__ __forceinline__ void cp_async16(unsigned smem_addr, const void* gptr) {
    asm volatile("cp.async.cg.shared.global [%0], [%1], 16;\n"
                 :: "r"(smem_addr), "l"(gptr));
}
__device__ __forceinline__ void cp_commit() {
    asm volatile("cp.async.commit_group;\n");
}
__device__ __forceinline__ void cp_wait2() {
    asm volatile("cp.async.wait_group 2;\n");
}

// -------------------------------------------------------------------------
// Kernel 1: HBV scan. One thread per (n, m) chain; 16000 threads total.
// Per-warp 3-stage cp.async pipeline: 4x LDG.128-equivalent bulk copies per
// warp-step (2048 contiguous bytes) into padded smem, then conflict-free LDS.
// -------------------------------------------------------------------------
__global__ void __launch_bounds__(128)
hbv_scan_kernel(const float* __restrict__ x,        // (T, N, 3)
                const float* __restrict__ praw) {   // (T, N, 16, M)
    __shared__ __align__(16) float sp[4][STAGES][STAGE_FLOATS];

    const int tid  = blockIdx.x * 128 + threadIdx.x; // exactly 16000 threads
    const int lane = threadIdx.x & 31;
    const int wrp  = threadIdx.x >> 5;

    const int n       = tid >> 2;        // consumer: basin
    const int m       = tid & 3;         // consumer: ensemble member
    const int n_local = lane >> 2;       // basin within warp (0..7)
    const int n0      = (tid >> 5) * 8;  // warp's first basin

    // producer: lane L copies 16-byte chunks c = j*32 + L (j = 0..3) of the
    // warp's 2048-byte param block; chunk c -> basin c/16, param-group c%15
    unsigned sdst[4];
    const float* gsrc[4];
#pragma unroll
    for (int j = 0; j < 4; ++j) {
        const int c = j * 32 + lane;
        sdst[j] = (unsigned)__cvta_generic_to_shared(
                      &sp[wrp][0][(c >> 4) * BSTRIDE + (c & 15) * 4]);
        gsrc[j] = praw + (size_t)n0 * 64 + (size_t)c * 4;
    }
    const unsigned stage_bytes = STAGE_FLOATS * 4;

    const float* xbase = x + (size_t)n * 3;
    const float* prd   = &sp[wrp][0][n_local * BSTRIDE + m];

    float SNOWPACK = 0.001f, MELTWATER = 0.001f, SM = 0.001f,
          SUZ = 0.001f, SLZ = 0.001f;

    float fb[STAGES][3];

    // prologue: fill 3 stages
#pragma unroll
    for (int s = 0; s < STAGES; ++s) {
        const size_t poff = (size_t)s * (NB * 64);
#pragma unroll
        for (int j = 0; j < 4; ++j)
            cp_async16(sdst[j] + s * stage_bytes, gsrc[j] + poff);
        cp_commit();
        const size_t xoff = (size_t)s * (NB * 3);
#pragma unroll
        for (int c = 0; c < 3; ++c)
            fb[s][c] = __ldg(xbase + xoff + c);
    }

    int s = 0;
    for (int t = 0; t < TT_STEPS; ++t) {
        cp_wait2();          // oldest group (stage s) complete
        __syncwarp();        // visible to all lanes

        // conflict-free scalar reads of this thread's 14 params
        float cur[14];
        const float* ps = prd + s * STAGE_FLOATS;
#pragma unroll
        for (int i = 0; i < 14; ++i)
            cur[i] = ps[i * 4];
        const float P   = fb[s][0];
        const float Ta  = fb[s][1];
        const float PET = fb[s][2];

        __syncwarp();        // all lanes done reading stage s

        // refill stage s with step t+3 (clamped; deterministic)
        {
            const int tn = (t + STAGES < TT_STEPS) ? (t + STAGES) : (TT_STEPS - 1);
            const size_t poff = (size_t)tn * (NB * 64);
#pragma unroll
            for (int j = 0; j < 4; ++j)
                cp_async16(sdst[j] + s * stage_bytes, gsrc[j] + poff);
            cp_commit();
            const size_t xoff = (size_t)tn * (NB * 3);
#pragma unroll
            for (int c = 0; c < 3; ++c)
                fb[s][c] = __ldg(xbase + xoff + c);
        }

        // ---- scale raw params to physical bounds ----
        const float BETA   = 1.0f   + 5.0f    * cur[0];
        const float FC     = 50.0f  + 950.0f  * cur[1];
        const float K0     = 0.05f  + 0.85f   * cur[2];
        const float K1     = 0.01f  + 0.49f   * cur[3];
        const float K2     = 0.001f + 0.199f  * cur[4];
        const float LP     = 0.2f   + 0.8f    * cur[5];
        const float PERC   =          10.0f   * cur[6];
        const float UZL    =          100.0f  * cur[7];
        const float TTp    = -2.5f  + 5.0f    * cur[8];
        const float CFMAX  = 0.5f   + 9.5f    * cur[9];
        const float CFR    =          0.1f    * cur[10];
        const float CWH    =          0.2f    * cur[11];
        const float BETAET = 0.3f   + 4.7f    * cur[12];
        const float Cc     =                    cur[13];

        // ---- HBV step (exact reference op order) ----
        const float RAIN = (Ta >= TTp) ? P : 0.0f;
        const float SNOW = (Ta <  TTp) ? P : 0.0f;
        SNOWPACK += SNOW;
        const float melt = fminf(fmaxf(CFMAX * (Ta - TTp), 0.0f), SNOWPACK);
        MELTWATER += melt;
        SNOWPACK = fmaxf(SNOWPACK - melt, 1e-5f);
        const float refreeze = fminf(fmaxf(CFR * CFMAX * (TTp - Ta), 0.0f), MELTWATER);
        SNOWPACK += refreeze;
        MELTWATER = fmaxf(MELTWATER - refreeze, 1e-5f);
        const float tosoil = fmaxf(MELTWATER - CWH * SNOWPACK, 0.0f);
        MELTWATER = fmaxf(MELTWATER - tosoil, 1e-5f);

        const float rFC = __fdividef(1.0f, FC);
        float soil_wet = __expf(BETA * __logf(SM * rFC));
        soil_wet = fminf(fmaxf(soil_wet, 0.0f), 1.0f);
        const float recharge = (RAIN + tosoil) * soil_wet;
        SM = SM + RAIN + tosoil - recharge;
        const float excess = fmaxf(SM - FC, 0.0f);
        SM = fmaxf(SM - excess, 1e-5f);

        float evapfactor = __expf(BETAET * __logf(SM * __fdividef(1.0f, LP * FC)));
        evapfactor = fminf(fmaxf(evapfactor, 0.0f), 1.0f);
        const float ETact = fminf(SM, PET * evapfactor);
        SM = fmaxf(SM - ETact, 1e-5f);

        const float capillary = fminf(SLZ, Cc * SLZ * (1.0f - fminf(SM * rFC, 1.0f)));
        SM += capillary;
        SLZ = fmaxf(SLZ - capillary, 1e-5f);

        SUZ += recharge + excess;
        const float PERCa = fminf(SUZ, PERC);
        SUZ -= PERCa;
        const float Q0 = K0 * fmaxf(SUZ - UZL, 0.0f);
        SUZ -= Q0;
        const float Q1 = K1 * SUZ;
        SUZ -= Q1;
        SLZ += PERCa;
        const float Q2 = K2 * SLZ;
        SLZ -= Q2;

        // mean over the 4 ensemble members (quad = adjacent lanes)
        float q = Q0 + Q1 + Q2;
        q += __shfl_xor_sync(0xffffffffu, q, 1);
        q += __shfl_xor_sync(0xffffffffu, q, 2);
        if (m == 0)
            g_qsim[(size_t)t * NB + n] = 0.25f * q;

        if (++s == STAGES) s = 0;
    }
}

// -------------------------------------------------------------------------
// Kernel 2: gamma unit-hydrograph weights per basin (normalized).
// -------------------------------------------------------------------------
__global__ void uh_kernel(const float* __restrict__ conv) {
    const int n = blockIdx.x * blockDim.x + threadIdx.x;
    if (n >= NB) return;
    const float a = conv[n * 2 + 0] * 2.9f;
    const float b = conv[n * 2 + 1] * 6.5f;
    const float aa    = fmaxf(a, 0.0f) + 0.1f;
    const float theta = fmaxf(b, 0.0f) + 0.5f;
    const float lg = lgammaf(aa);
    const float lt = logf(theta);
    const float rth = 1.0f / theta;

    float w[LENF];
    float s = 0.0f;
#pragma unroll
    for (int k = 0; k < LENF; ++k) {
        const float tt = 0.5f + (float)k;
        w[k] = expf(-lg - aa * lt + (aa - 1.0f) * logf(tt) - tt * rth);
        s += w[k];
    }
    const float rs = 1.0f / s;
#pragma unroll
    for (int k = 0; k < LENF; ++k)
        g_uh[k * NB + n] = w[k] * rs;
}

// -------------------------------------------------------------------------
// Kernel 3: 15-tap causal FIR routing. One thread per (t, n) output.
// -------------------------------------------------------------------------
__global__ void rout_kernel(float* __restrict__ out) {
    const int idx = blockIdx.x * blockDim.x + threadIdx.x;
    if (idx >= TT_STEPS * NB) return;
    const int t = idx / NB;
    const int n = idx - t * NB;

    float acc = 0.0f;
#pragma unroll
    for (int k = 0; k < LENF; ++k) {
        if (k <= t)
            acc += __ldg(&g_uh[k * NB + n]) * __ldg(&g_qsim[(size_t)(t - k) * NB + n]);
    }
    out[idx] = acc;
}

// -------------------------------------------------------------------------
extern "C" void kernel_launch(void* const* d_in, const int* in_sizes, int n_in,
                              void* d_out, int out_size) {
    const float* x    = (const float*)d_in[0];   // (365, 4000, 3)
    const float* praw = (const float*)d_in[1];   // (365, 4000, 16, 4)
    const float* conv = (const float*)d_in[2];   // (4000, 2)
    float* out = (float*)d_out;                  // (365, 4000)

    hbv_scan_kernel<<<(NB * MM) / 128, 128>>>(x, praw);
    uh_kernel<<<(NB + 127) / 128, 128>>>(conv);
    rout_kernel<<<(TT_STEPS * NB + 255) / 256, 256>>>(out);
}

// round 9
// speedup vs baseline: 2.1697x; 1.8301x over previous
#include <cuda_runtime.h>
#include <cstddef>

#define TT_STEPS 365
#define NB 4000
#define MM 4
#define LENF 15

// Scratch (allocation-free: __device__ globals)
__device__ float g_qsim[TT_STEPS * NB];   // mean-over-M runoff per (t, n)
__device__ float g_uh[LENF * NB];         // routing weights per (k, n)

#define STAGES 5                          // 365 % 5 == 0 -> compile-time stage idx
#define BSTRIDE 68                        // 64 floats + 4 pad -> conflict-free LDS
#define STAGE_FLOATS (8 * BSTRIDE)        // 544 floats = 2176 B per warp-stage

__device__ __forceinline__ void cp_async16(unsigned smem_addr, const void* gptr) {
    asm volatile("cp.async.cg.shared.global [%0], [%1], 16;\n"
                 :: "r"(smem_addr), "l"(gptr));
}
__device__ __forceinline__ void cp_commit() {
    asm volatile("cp.async.commit_group;\n");
}
#define CP_WAIT_GROUP(nrem) asm volatile("cp.async.wait_group %0;\n" :: "n"(nrem))

// -------------------------------------------------------------------------
// Kernel 1: HBV scan. One thread per (n, m) chain; 16000 threads total.
// 5-stage cp.async ring with FULLY STATIC stage indices (loop unrolled x5),
// so no dynamic array indexing, no local memory, max scheduler freedom.
// -------------------------------------------------------------------------
struct HBVState {
    float SNOWPACK, MELTWATER, SM, SUZ, SLZ;
};

__device__ __forceinline__ void hbv_step(HBVState& st,
                                         const float cur[14],
                                         float P, float Ta, float PET,
                                         int t, int n, int m) {
    const float BETA   = 1.0f   + 5.0f    * cur[0];
    const float FC     = 50.0f  + 950.0f  * cur[1];
    const float K0     = 0.05f  + 0.85f   * cur[2];
    const float K1     = 0.01f  + 0.49f   * cur[3];
    const float K2     = 0.001f + 0.199f  * cur[4];
    const float LP     = 0.2f   + 0.8f    * cur[5];
    const float PERC   =          10.0f   * cur[6];
    const float UZL    =          100.0f  * cur[7];
    const float TTp    = -2.5f  + 5.0f    * cur[8];
    const float CFMAX  = 0.5f   + 9.5f    * cur[9];
    const float CFR    =          0.1f    * cur[10];
    const float CWH    =          0.2f    * cur[11];
    const float BETAET = 0.3f   + 4.7f    * cur[12];
    const float Cc     =                    cur[13];

    const float RAIN = (Ta >= TTp) ? P : 0.0f;
    const float SNOW = (Ta <  TTp) ? P : 0.0f;
    st.SNOWPACK += SNOW;
    const float melt = fminf(fmaxf(CFMAX * (Ta - TTp), 0.0f), st.SNOWPACK);
    st.MELTWATER += melt;
    st.SNOWPACK = fmaxf(st.SNOWPACK - melt, 1e-5f);
    const float refreeze = fminf(fmaxf(CFR * CFMAX * (TTp - Ta), 0.0f), st.MELTWATER);
    st.SNOWPACK += refreeze;
    st.MELTWATER = fmaxf(st.MELTWATER - refreeze, 1e-5f);
    const float tosoil = fmaxf(st.MELTWATER - CWH * st.SNOWPACK, 0.0f);
    st.MELTWATER = fmaxf(st.MELTWATER - tosoil, 1e-5f);

    const float rFC = __fdividef(1.0f, FC);
    float soil_wet = __expf(BETA * __logf(st.SM * rFC));
    soil_wet = fminf(fmaxf(soil_wet, 0.0f), 1.0f);
    const float recharge = (RAIN + tosoil) * soil_wet;
    st.SM = st.SM + RAIN + tosoil - recharge;
    const float excess = fmaxf(st.SM - FC, 0.0f);
    st.SM = fmaxf(st.SM - excess, 1e-5f);

    float evapfactor = __expf(BETAET * __logf(st.SM * __fdividef(1.0f, LP * FC)));
    evapfactor = fminf(fmaxf(evapfactor, 0.0f), 1.0f);
    const float ETact = fminf(st.SM, PET * evapfactor);
    st.SM = fmaxf(st.SM - ETact, 1e-5f);

    const float capillary = fminf(st.SLZ, Cc * st.SLZ * (1.0f - fminf(st.SM * rFC, 1.0f)));
    st.SM += capillary;
    st.SLZ = fmaxf(st.SLZ - capillary, 1e-5f);

    st.SUZ += recharge + excess;
    const float PERCa = fminf(st.SUZ, PERC);
    st.SUZ -= PERCa;
    const float Q0 = K0 * fmaxf(st.SUZ - UZL, 0.0f);
    st.SUZ -= Q0;
    const float Q1 = K1 * st.SUZ;
    st.SUZ -= Q1;
    st.SLZ += PERCa;
    const float Q2 = K2 * st.SLZ;
    st.SLZ -= Q2;

    float q = Q0 + Q1 + Q2;
    q += __shfl_xor_sync(0xffffffffu, q, 1);
    q += __shfl_xor_sync(0xffffffffu, q, 2);
    if (m == 0)
        g_qsim[(size_t)t * NB + n] = 0.25f * q;
}

__global__ void __launch_bounds__(128)
hbv_scan_kernel(const float* __restrict__ x,        // (T, N, 3)
                const float* __restrict__ praw) {   // (T, N, 16, M)
    __shared__ __align__(16) float sp[4][STAGES][STAGE_FLOATS];

    const int tid  = blockIdx.x * 128 + threadIdx.x; // exactly 16000 threads
    const int lane = threadIdx.x & 31;
    const int wrp  = threadIdx.x >> 5;

    const int n       = tid >> 2;        // consumer: basin
    const int m       = tid & 3;         // consumer: ensemble member
    const int n_local = lane >> 2;       // basin within warp (0..7)
    const int n0      = (tid >> 5) * 8;  // warp's first basin

    // producer: lane L copies 16-byte chunks c = j*32 + L (j = 0..3) of the
    // warp's 2048-byte param block
    unsigned sdst[4];
    const float* gsrc[4];
#pragma unroll
    for (int j = 0; j < 4; ++j) {
        const int c = j * 32 + lane;
        sdst[j] = (unsigned)__cvta_generic_to_shared(
                      &sp[wrp][0][(c >> 4) * BSTRIDE + (c & 15) * 4]);
        gsrc[j] = praw + (size_t)n0 * 64 + (size_t)c * 4;
    }
    const unsigned stage_bytes = STAGE_FLOATS * 4;

    const float* xbase = x + (size_t)n * 3;
    const float* prd   = &sp[wrp][0][n_local * BSTRIDE + m];

    HBVState st = {0.001f, 0.001f, 0.001f, 0.001f, 0.001f};

    float fb[STAGES][3];   // statically indexed everywhere below

    // prologue: fill 5 stages with t = 0..4
#pragma unroll
    for (int s = 0; s < STAGES; ++s) {
        const size_t poff = (size_t)s * (NB * 64);
#pragma unroll
        for (int j = 0; j < 4; ++j)
            cp_async16(sdst[j] + s * stage_bytes, gsrc[j] + poff);
        cp_commit();
        const size_t xoff = (size_t)s * (NB * 3);
#pragma unroll
        for (int c = 0; c < 3; ++c)
            fb[s][c] = __ldg(xbase + xoff + c);
    }

    // main loop: 73 iterations x 5 statically-staged steps
    for (int tb = 0; tb < TT_STEPS; tb += STAGES) {
#pragma unroll
        for (int s = 0; s < STAGES; ++s) {
            const int t = tb + s;

            CP_WAIT_GROUP(STAGES - 1);   // oldest group (stage s) complete
            __syncwarp();

            float cur[14];
            const float* ps = prd + s * STAGE_FLOATS;
#pragma unroll
            for (int i = 0; i < 14; ++i)
                cur[i] = ps[i * 4];
            const float P   = fb[s][0];
            const float Ta  = fb[s][1];
            const float PET = fb[s][2];

            __syncwarp();                // all lanes done reading stage s

            // refill stage s with step t+5 (clamped; deterministic)
            {
                const int tn = (t + STAGES < TT_STEPS) ? (t + STAGES) : (TT_STEPS - 1);
                const size_t poff = (size_t)tn * (NB * 64);
#pragma unroll
                for (int j = 0; j < 4; ++j)
                    cp_async16(sdst[j] + s * stage_bytes, gsrc[j] + poff);
                cp_commit();
                const size_t xoff = (size_t)tn * (NB * 3);
#pragma unroll
                for (int c = 0; c < 3; ++c)
                    fb[s][c] = __ldg(xbase + xoff + c);
            }

            hbv_step(st, cur, P, Ta, PET, t, n, m);
        }
    }
}

// -------------------------------------------------------------------------
// Kernel 2: gamma unit-hydrograph weights per basin (normalized).
// -------------------------------------------------------------------------
__global__ void uh_kernel(const float* __restrict__ conv) {
    const int n = blockIdx.x * blockDim.x + threadIdx.x;
    if (n >= NB) return;
    const float a = conv[n * 2 + 0] * 2.9f;
    const float b = conv[n * 2 + 1] * 6.5f;
    const float aa    = fmaxf(a, 0.0f) + 0.1f;
    const float theta = fmaxf(b, 0.0f) + 0.5f;
    const float lg = lgammaf(aa);
    const float lt = logf(theta);
    const float rth = 1.0f / theta;

    float w[LENF];
    float s = 0.0f;
#pragma unroll
    for (int k = 0; k < LENF; ++k) {
        const float tt = 0.5f + (float)k;
        w[k] = expf(-lg - aa * lt + (aa - 1.0f) * logf(tt) - tt * rth);
        s += w[k];
    }
    const float rs = 1.0f / s;
#pragma unroll
    for (int k = 0; k < LENF; ++k)
        g_uh[k * NB + n] = w[k] * rs;
}

// -------------------------------------------------------------------------
// Kernel 3: 15-tap causal FIR routing. One thread per (t, n) output.
// -------------------------------------------------------------------------
__global__ void rout_kernel(float* __restrict__ out) {
    const int idx = blockIdx.x * blockDim.x + threadIdx.x;
    if (idx >= TT_STEPS * NB) return;
    const int t = idx / NB;
    const int n = idx - t * NB;

    float acc = 0.0f;
#pragma unroll
    for (int k = 0; k < LENF; ++k) {
        if (k <= t)
            acc += __ldg(&g_uh[k * NB + n]) * __ldg(&g_qsim[(size_t)(t - k) * NB + n]);
    }
    out[idx] = acc;
}

// -------------------------------------------------------------------------
extern "C" void kernel_launch(void* const* d_in, const int* in_sizes, int n_in,
                              void* d_out, int out_size) {
    const float* x    = (const float*)d_in[0];   // (365, 4000, 3)
    const float* praw = (const float*)d_in[1];   // (365, 4000, 16, 4)
    const float* conv = (const float*)d_in[2];   // (4000, 2)
    float* out = (float*)d_out;                  // (365, 4000)

    hbv_scan_kernel<<<(NB * MM) / 128, 128>>>(x, praw);
    uh_kernel<<<(NB + 127) / 128, 128>>>(conv);
    rout_kernel<<<(TT_STEPS * NB + 255) / 256, 256>>>(out);
}

// round 10
// speedup vs baseline: 2.2777x; 1.0498x over previous
#include <cuda_runtime.h>
#include <cstddef>

#define TT_STEPS 365
#define NB 4000
#define MM 4
#define LENF 15

// Scratch (allocation-free: __device__ globals)
__device__ float g_qsim[TT_STEPS * NB];   // mean-over-M runoff per (t, n)
__device__ float g_uh[LENF * NB];         // routing weights per (k, n)

#define STAGES 5                          // 365 % 5 == 0 -> compile-time stage idx
#define BSTRIDE 68                        // 64 floats + 4 pad -> conflict-free LDS
#define STAGE_FLOATS (8 * BSTRIDE)        // 544 floats = 2176 B per warp-stage

__device__ __forceinline__ void cp_async16(unsigned smem_addr, const void* gptr) {
    asm volatile("cp.async.cg.shared.global [%0], [%1], 16;\n"
                 :: "r"(smem_addr), "l"(gptr));
}
__device__ __forceinline__ void cp_commit() {
    asm volatile("cp.async.commit_group;\n");
}
#define CP_WAIT_GROUP(nrem) asm volatile("cp.async.wait_group %0;\n" :: "n"(nrem))

// -------------------------------------------------------------------------
// Kernel 1: HBV scan. One thread per (n, m) chain; 16000 threads total.
// 5-stage cp.async ring (static stage indices) + REGISTER double-buffering
// of the params: step t+1's 14 params are LDS'd into `pn` while step t's
// math runs, so only the true state recurrence is serial.
// -------------------------------------------------------------------------
struct HBVState {
    float SNOWPACK, MELTWATER, SM, SUZ, SLZ;
};

__device__ __forceinline__ void hbv_step(HBVState& st,
                                         const float cur[14],
                                         float P, float Ta, float PET,
                                         int t, int n, int m) {
    const float BETA   = 1.0f   + 5.0f    * cur[0];
    const float FC     = 50.0f  + 950.0f  * cur[1];
    const float K0     = 0.05f  + 0.85f   * cur[2];
    const float K1     = 0.01f  + 0.49f   * cur[3];
    const float K2     = 0.001f + 0.199f  * cur[4];
    const float LP     = 0.2f   + 0.8f    * cur[5];
    const float PERC   =          10.0f   * cur[6];
    const float UZL    =          100.0f  * cur[7];
    const float TTp    = -2.5f  + 5.0f    * cur[8];
    const float CFMAX  = 0.5f   + 9.5f    * cur[9];
    const float CFR    =          0.1f    * cur[10];
    const float CWH    =          0.2f    * cur[11];
    const float BETAET = 0.3f   + 4.7f    * cur[12];
    const float Cc     =                    cur[13];

    const float RAIN = (Ta >= TTp) ? P : 0.0f;
    const float SNOW = (Ta <  TTp) ? P : 0.0f;
    st.SNOWPACK += SNOW;
    const float melt = fminf(fmaxf(CFMAX * (Ta - TTp), 0.0f), st.SNOWPACK);
    st.MELTWATER += melt;
    st.SNOWPACK = fmaxf(st.SNOWPACK - melt, 1e-5f);
    const float refreeze = fminf(fmaxf(CFR * CFMAX * (TTp - Ta), 0.0f), st.MELTWATER);
    st.SNOWPACK += refreeze;
    st.MELTWATER = fmaxf(st.MELTWATER - refreeze, 1e-5f);
    const float tosoil = fmaxf(st.MELTWATER - CWH * st.SNOWPACK, 0.0f);
    st.MELTWATER = fmaxf(st.MELTWATER - tosoil, 1e-5f);

    const float rFC   = __fdividef(1.0f, FC);
    const float rLPFC = __fdividef(1.0f, LP * FC);   // param-only: hoistable

    float soil_wet = __expf(BETA * __logf(st.SM * rFC));
    soil_wet = fminf(fmaxf(soil_wet, 0.0f), 1.0f);
    const float recharge = (RAIN + tosoil) * soil_wet;
    st.SM = st.SM + RAIN + tosoil - recharge;
    const float excess = fmaxf(st.SM - FC, 0.0f);
    st.SM = fmaxf(st.SM - excess, 1e-5f);

    float evapfactor = __expf(BETAET * __logf(st.SM * rLPFC));
    evapfactor = fminf(fmaxf(evapfactor, 0.0f), 1.0f);
    const float ETact = fminf(st.SM, PET * evapfactor);
    st.SM = fmaxf(st.SM - ETact, 1e-5f);

    const float capillary = fminf(st.SLZ, Cc * st.SLZ * (1.0f - fminf(st.SM * rFC, 1.0f)));
    st.SM += capillary;
    st.SLZ = fmaxf(st.SLZ - capillary, 1e-5f);

    st.SUZ += recharge + excess;
    const float PERCa = fminf(st.SUZ, PERC);
    st.SUZ -= PERCa;
    const float Q0 = K0 * fmaxf(st.SUZ - UZL, 0.0f);
    st.SUZ -= Q0;
    const float Q1 = K1 * st.SUZ;
    st.SUZ -= Q1;
    st.SLZ += PERCa;
    const float Q2 = K2 * st.SLZ;
    st.SLZ -= Q2;

    float q = Q0 + Q1 + Q2;
    q += __shfl_xor_sync(0xffffffffu, q, 1);
    q += __shfl_xor_sync(0xffffffffu, q, 2);
    if (m == 0)
        g_qsim[(size_t)t * NB + n] = 0.25f * q;
}

__global__ void __launch_bounds__(128)
hbv_scan_kernel(const float* __restrict__ x,        // (T, N, 3)
                const float* __restrict__ praw) {   // (T, N, 16, M)
    __shared__ __align__(16) float sp[4][STAGES][STAGE_FLOATS];

    const int tid  = blockIdx.x * 128 + threadIdx.x; // exactly 16000 threads
    const int lane = threadIdx.x & 31;
    const int wrp  = threadIdx.x >> 5;

    const int n       = tid >> 2;        // consumer: basin
    const int m       = tid & 3;         // consumer: ensemble member
    const int n_local = lane >> 2;       // basin within warp (0..7)
    const int n0      = (tid >> 5) * 8;  // warp's first basin

    // producer: lane L copies 16-byte chunks c = j*32 + L (j = 0..3) of the
    // warp's 2048-byte param block
    unsigned sdst[4];
    const float* gsrc[4];
#pragma unroll
    for (int j = 0; j < 4; ++j) {
        const int c = j * 32 + lane;
        sdst[j] = (unsigned)__cvta_generic_to_shared(
                      &sp[wrp][0][(c >> 4) * BSTRIDE + (c & 15) * 4]);
        gsrc[j] = praw + (size_t)n0 * 64 + (size_t)c * 4;
    }
    const unsigned stage_bytes = STAGE_FLOATS * 4;

    const float* xbase = x + (size_t)n * 3;
    const float* prd   = &sp[wrp][0][n_local * BSTRIDE + m];

    HBVState st = {0.001f, 0.001f, 0.001f, 0.001f, 0.001f};

    float fb[STAGES][3];   // statically indexed everywhere below

    // prologue: fill 5 stages with t = 0..4
#pragma unroll
    for (int s = 0; s < STAGES; ++s) {
        const size_t poff = (size_t)s * (NB * 64);
#pragma unroll
        for (int j = 0; j < 4; ++j)
            cp_async16(sdst[j] + s * stage_bytes, gsrc[j] + poff);
        cp_commit();
        const size_t xoff = (size_t)s * (NB * 3);
#pragma unroll
        for (int c = 0; c < 3; ++c)
            fb[s][c] = __ldg(xbase + xoff + c);
    }

    // register double-buffer for params: pc = step t, pn = step t+1
    float pc[14], pn[14];

    // prime pc with stage 0 (t = 0)
    CP_WAIT_GROUP(STAGES - 1);
    __syncwarp();
#pragma unroll
    for (int i = 0; i < 14; ++i)
        pc[i] = prd[i * 4];

    // main loop: 73 iterations x 5 statically-staged steps
    for (int tb = 0; tb < TT_STEPS; tb += STAGES) {
#pragma unroll
        for (int s = 0; s < STAGES; ++s) {
            const int t  = tb + s;
            const int s1 = (s + 1 == STAGES) ? 0 : (s + 1);

            // stage s+1 (params of t+1) is complete once <=3 groups remain
            CP_WAIT_GROUP(STAGES - 2);
            __syncwarp();

            // prefetch NEXT step's params into registers
            const float* ps1 = prd + s1 * STAGE_FLOATS;
#pragma unroll
            for (int i = 0; i < 14; ++i)
                pn[i] = ps1[i * 4];

            // this step's forcings (register-resident, prefetched 5 ahead)
            const float P   = fb[s][0];
            const float Ta  = fb[s][1];
            const float PET = fb[s][2];

            // refill stage s with step t+5 (its buffer was consumed at t-1)
            {
                const int tn = (t + STAGES < TT_STEPS) ? (t + STAGES) : (TT_STEPS - 1);
                const size_t poff = (size_t)tn * (NB * 64);
#pragma unroll
                for (int j = 0; j < 4; ++j)
                    cp_async16(sdst[j] + s * stage_bytes, gsrc[j] + poff);
                cp_commit();
                const size_t xoff = (size_t)tn * (NB * 3);
#pragma unroll
                for (int c = 0; c < 3; ++c)
                    fb[s][c] = __ldg(xbase + xoff + c);
            }

            hbv_step(st, pc, P, Ta, PET, t, n, m);

            // rotate register buffers (renamed away by ptxas)
#pragma unroll
            for (int i = 0; i < 14; ++i)
                pc[i] = pn[i];
        }
    }
}

// -------------------------------------------------------------------------
// Kernel 2: gamma unit-hydrograph weights per basin (normalized).
// -------------------------------------------------------------------------
__global__ void uh_kernel(const float* __restrict__ conv) {
    const int n = blockIdx.x * blockDim.x + threadIdx.x;
    if (n >= NB) return;
    const float a = conv[n * 2 + 0] * 2.9f;
    const float b = conv[n * 2 + 1] * 6.5f;
    const float aa    = fmaxf(a, 0.0f) + 0.1f;
    const float theta = fmaxf(b, 0.0f) + 0.5f;
    const float lg = lgammaf(aa);
    const float lt = logf(theta);
    const float rth = 1.0f / theta;

    float w[LENF];
    float s = 0.0f;
#pragma unroll
    for (int k = 0; k < LENF; ++k) {
        const float tt = 0.5f + (float)k;
        w[k] = expf(-lg - aa * lt + (aa - 1.0f) * logf(tt) - tt * rth);
        s += w[k];
    }
    const float rs = 1.0f / s;
#pragma unroll
    for (int k = 0; k < LENF; ++k)
        g_uh[k * NB + n] = w[k] * rs;
}

// -------------------------------------------------------------------------
// Kernel 3: 15-tap causal FIR routing. One thread per (t, n) output.
// -------------------------------------------------------------------------
__global__ void rout_kernel(float* __restrict__ out) {
    const int idx = blockIdx.x * blockDim.x + threadIdx.x;
    if (idx >= TT_STEPS * NB) return;
    const int t = idx / NB;
    const int n = idx - t * NB;

    float acc = 0.0f;
#pragma unroll
    for (int k = 0; k < LENF; ++k) {
        if (k <= t)
            acc += __ldg(&g_uh[k * NB + n]) * __ldg(&g_qsim[(size_t)(t - k) * NB + n]);
    }
    out[idx] = acc;
}

// -------------------------------------------------------------------------
extern "C" void kernel_launch(void* const* d_in, const int* in_sizes, int n_in,
                              void* d_out, int out_size) {
    const float* x    = (const float*)d_in[0];   // (365, 4000, 3)
    const float* praw = (const float*)d_in[1];   // (365, 4000, 16, 4)
    const float* conv = (const float*)d_in[2];   // (4000, 2)
    float* out = (float*)d_out;                  // (365, 4000)

    hbv_scan_kernel<<<(NB * MM) / 128, 128>>>(x, praw);
    uh_kernel<<<(NB + 127) / 128, 128>>>(conv);
    rout_kernel<<<(TT_STEPS * NB + 255) / 256, 256>>>(out);
}